// round 1
// baseline (speedup 1.0000x reference)
#include <cuda_runtime.h>

#define NN 8192
#define D 64
#define ALPHA 0.2f

// Scratch (no allocation allowed)
__device__ float g_h[NN * D];
__device__ float g_f1[NN];
__device__ float g_f2[NN];
__device__ float g_f2s[NN];
__device__ int   g_perm[NN];
__device__ float g_wlo[NN];   // exp(alpha * f2_sorted)
__device__ float g_whi[NN];   // exp(f2_sorted)
__device__ float g_LoP[(NN + 1) * D];  // prefix sums of wlo*h (sorted order), exclusive
__device__ float g_HiS[(NN + 1) * D];  // suffix sums of whi*h (sorted order), inclusive-from-k
__device__ float g_zLo[NN + 1];
__device__ float g_zHi[NN + 1];

// ---------------- Kernel A: h = x @ Wt ----------------
__global__ void kA(const float* __restrict__ x, const float* __restrict__ Wt) {
    __shared__ float sW[D * D];
    __shared__ float sx[4][D];
    int tid = threadIdx.x;  // 256
    for (int i = tid; i < D * D; i += 256) sW[i] = Wt[i];
    int r = tid >> 6, o = tid & 63;
    int row = blockIdx.x * 4 + r;
    sx[r][o] = x[row * D + o];
    __syncthreads();
    float acc = 0.f;
#pragma unroll
    for (int i = 0; i < D; i++) acc += sx[r][i] * sW[i * D + o];
    g_h[row * D + o] = acc;
}

// ---------------- Kernel A2: f1 = h@a1+b1, f2 = h@a2+b2 ----------------
__global__ void kA2(const float* __restrict__ a1, const float* __restrict__ b1,
                    const float* __restrict__ a2, const float* __restrict__ b2) {
    int w = threadIdx.x >> 5, lane = threadIdx.x & 31;
    int i = blockIdx.x * 8 + w;
    float h0 = g_h[i * D + lane], h1 = g_h[i * D + lane + 32];
    float s1 = h0 * a1[lane] + h1 * a1[lane + 32];
    float s2 = h0 * a2[lane] + h1 * a2[lane + 32];
#pragma unroll
    for (int o = 16; o; o >>= 1) {
        s1 += __shfl_down_sync(0xFFFFFFFFu, s1, o);
        s2 += __shfl_down_sync(0xFFFFFFFFu, s2, o);
    }
    if (lane == 0) {
        g_f1[i] = s1 + b1[0];
        g_f2[i] = s2 + b2[0];
    }
}

// ---------------- Kernel B: bitonic sort (f2, idx) in 64KB smem ----------------
__global__ void kSort() {
    extern __shared__ unsigned long long sk[];
    int tid = threadIdx.x;  // 1024
    for (int i = tid; i < NN; i += 1024) {
        unsigned u = __float_as_uint(g_f2[i]);
        u = (u >> 31) ? ~u : (u | 0x80000000u);  // order-preserving map
        sk[i] = ((unsigned long long)u << 32) | (unsigned)i;
    }
    __syncthreads();
    for (int k = 2; k <= NN; k <<= 1) {
        for (int j = k >> 1; j > 0; j >>= 1) {
            for (int i = tid; i < NN; i += 1024) {
                int ixj = i ^ j;
                if (ixj > i) {
                    bool asc = ((i & k) == 0);
                    unsigned long long a = sk[i], b = sk[ixj];
                    if ((a > b) == asc) { sk[i] = b; sk[ixj] = a; }
                }
            }
            __syncthreads();
        }
    }
    for (int i = tid; i < NN; i += 1024) {
        unsigned long long kv = sk[i];
        int idx = (int)(kv & 0xFFFFFFFFu);
        g_perm[i] = idx;
        float f = g_f2[idx];
        g_f2s[i] = f;
        g_wlo[i] = expf(ALPHA * f);
        g_whi[i] = expf(f);
    }
}

// ---------------- Kernel C: 130 column scans (64 fwd, 64 bwd, 2 scalar) ----------------
__global__ void kScan() {
    int wg = blockIdx.x * 4 + (threadIdx.x >> 5);
    int lane = threadIdx.x & 31;
    if (wg >= 130) return;
    const unsigned FULL = 0xFFFFFFFFu;

    if (wg < 64) {  // forward scan: LoP[(j+1)*D+d] = sum_{j'<=j} wlo*h
        int d = wg;
        if (lane == 0) g_LoP[d] = 0.f;
        double carry = 0.0;
        for (int base = 0; base < NN; base += 256) {
            int j0 = base + lane * 8;
            float v[8];
#pragma unroll
            for (int m = 0; m < 8; m++) v[m] = g_wlo[j0 + m] * g_h[g_perm[j0 + m] * D + d];
            float run = 0.f;
#pragma unroll
            for (int m = 0; m < 8; m++) { run += v[m]; v[m] = run; }
            float x = run;
#pragma unroll
            for (int o = 1; o < 32; o <<= 1) { float t = __shfl_up_sync(FULL, x, o); if (lane >= o) x += t; }
            float total = __shfl_sync(FULL, x, 31);
            float off = (float)carry + (x - run);
#pragma unroll
            for (int m = 0; m < 8; m++) g_LoP[(j0 + m + 1) * D + d] = off + v[m];
            carry += (double)total;
        }
    } else if (wg < 128) {  // backward scan: HiS[j*D+d] = sum_{j'>=j} whi*h
        int d = wg - 64;
        if (lane == 0) g_HiS[NN * D + d] = 0.f;
        double carry = 0.0;
        for (int base = NN - 256; base >= 0; base -= 256) {
            int j0 = base + lane * 8;
            float v[8];
#pragma unroll
            for (int m = 0; m < 8; m++) v[m] = g_whi[j0 + m] * g_h[g_perm[j0 + m] * D + d];
            float run = 0.f;
#pragma unroll
            for (int m = 7; m >= 0; m--) { run += v[m]; v[m] = run; }
            float x = run;
#pragma unroll
            for (int o = 1; o < 32; o <<= 1) { float t = __shfl_down_sync(FULL, x, o); if (lane + o < 32) x += t; }
            float total = __shfl_sync(FULL, x, 0);
            float off = (float)carry + (x - run);
#pragma unroll
            for (int m = 0; m < 8; m++) g_HiS[(j0 + m) * D + d] = off + v[m];
            carry += (double)total;
        }
    } else if (wg == 128) {  // zLo forward
        if (lane == 0) g_zLo[0] = 0.f;
        double carry = 0.0;
        for (int base = 0; base < NN; base += 256) {
            int j0 = base + lane * 8;
            float v[8];
#pragma unroll
            for (int m = 0; m < 8; m++) v[m] = g_wlo[j0 + m];
            float run = 0.f;
#pragma unroll
            for (int m = 0; m < 8; m++) { run += v[m]; v[m] = run; }
            float x = run;
#pragma unroll
            for (int o = 1; o < 32; o <<= 1) { float t = __shfl_up_sync(FULL, x, o); if (lane >= o) x += t; }
            float total = __shfl_sync(FULL, x, 31);
            float off = (float)carry + (x - run);
#pragma unroll
            for (int m = 0; m < 8; m++) g_zLo[j0 + m + 1] = off + v[m];
            carry += (double)total;
        }
    } else {  // zHi backward
        if (lane == 0) g_zHi[NN] = 0.f;
        double carry = 0.0;
        for (int base = NN - 256; base >= 0; base -= 256) {
            int j0 = base + lane * 8;
            float v[8];
#pragma unroll
            for (int m = 0; m < 8; m++) v[m] = g_whi[j0 + m];
            float run = 0.f;
#pragma unroll
            for (int m = 7; m >= 0; m--) { run += v[m]; v[m] = run; }
            float x = run;
#pragma unroll
            for (int o = 1; o < 32; o <<= 1) { float t = __shfl_down_sync(FULL, x, o); if (lane + o < 32) x += t; }
            float total = __shfl_sync(FULL, x, 0);
            float off = (float)carry + (x - run);
#pragma unroll
            for (int m = 0; m < 8; m++) g_zHi[j0 + m] = off + v[m];
            carry += (double)total;
        }
    }
}

// ---------------- Kernel D: per-row combine + ELU ----------------
__global__ void kOut(float* __restrict__ out) {
    int w = threadIdx.x >> 5, lane = threadIdx.x & 31;
    int i = blockIdx.x * 8 + w;
    float f1 = g_f1[i];
    float t = -f1;
    int k = 0;
    if (lane == 0) {
        int lo = 0, hi = NN;
        while (lo < hi) { int m = (lo + hi) >> 1; if (g_f2s[m] <= t) lo = m + 1; else hi = m; }
        k = lo;
    }
    k = __shfl_sync(0xFFFFFFFFu, k, 0);
    float e1 = expf(f1), ea = expf(ALPHA * f1);
    float den = e1 * g_zHi[k] + ea * g_zLo[k];
    float inv = 1.0f / den;
#pragma unroll
    for (int p = 0; p < 2; p++) {
        int d = lane + 32 * p;
        float num = e1 * g_HiS[k * D + d] + ea * g_LoP[k * D + d];
        float r = num * inv;
        out[i * D + d] = (r > 0.f) ? r : (expf(r) - 1.f);
    }
}

extern "C" void kernel_launch(void* const* d_in, const int* in_sizes, int n_in,
                              void* d_out, int out_size) {
    const float* x  = (const float*)d_in[0];
    const float* Wt = (const float*)d_in[1];
    const float* a1 = (const float*)d_in[2];
    const float* b1 = (const float*)d_in[3];
    const float* a2 = (const float*)d_in[4];
    const float* b2 = (const float*)d_in[5];
    float* out = (float*)d_out;

    cudaFuncSetAttribute(kSort, cudaFuncAttributeMaxDynamicSharedMemorySize, NN * 8);

    kA<<<NN / 4, 256>>>(x, Wt);
    kA2<<<NN / 8, 256>>>(a1, b1, a2, b2);
    kSort<<<1, 1024, NN * 8>>>();
    kScan<<<33, 128>>>();
    kOut<<<NN / 8, 256>>>(out);
}

// round 2
// speedup vs baseline: 4.6556x; 4.6556x over previous
#include <cuda_runtime.h>

#define NN 8192
#define D 64
#define ALPHA 0.2f
#define CS 128   // scan chunk size
#define NC 64    // number of chunks (NN/CS)

// ---------------- device scratch (no allocation allowed) ----------------
__device__ float g_h[NN * D];
__device__ float g_f1[NN];
__device__ float g_f2[NN];
__device__ unsigned long long g_key[NN];
__device__ int   g_rank[NN];
__device__ int   g_perm[NN];
__device__ float g_f2s[NN];
__device__ float g_wlo[NN];            // exp(alpha * f2) in sorted order
__device__ float g_whi[NN];            // exp(f2) in sorted order
__device__ float g_LoP[(NN + 1) * D];  // chunk-local fwd prefix of wlo*h
__device__ float g_HiS[(NN + 1) * D];  // chunk-local bwd suffix of whi*h
__device__ float g_zLo[NN + 1];
__device__ float g_zHi[NN + 1];
__device__ float g_ofLo[D * NC];       // per (d, chunk): S1 totals -> S2 exclusive offsets
__device__ float g_ofHi[D * NC];
__device__ float g_ofzLo[NC];
__device__ float g_ofzHi[NC];

// ---------------- k1: h = x@Wt, f1/f2, sort keys, zero ranks ----------------
__global__ void k1(const float* __restrict__ x, const float* __restrict__ Wt,
                   const float* __restrict__ a1, const float* __restrict__ b1,
                   const float* __restrict__ a2, const float* __restrict__ b2) {
    __shared__ float sW[D * D];   // 16KB
    __shared__ float sx[16][D];   // 4KB
    __shared__ float sh[16][D];   // 4KB
    int tid = threadIdx.x;        // 256
    int row0 = blockIdx.x * 16;
    for (int i = tid; i < D * D; i += 256) sW[i] = Wt[i];
    for (int i = tid; i < 16 * D; i += 256) sx[i >> 6][i & 63] = x[row0 * D + i];
    __syncthreads();
    int o = tid & 63, rg = tid >> 6;  // rg handles rows rg*4 .. rg*4+3
    float a0 = 0.f, a1c = 0.f, a2c = 0.f, a3 = 0.f;
#pragma unroll
    for (int i = 0; i < D; i++) {
        float w = sW[i * D + o];
        a0  += sx[rg * 4 + 0][i] * w;
        a1c += sx[rg * 4 + 1][i] * w;
        a2c += sx[rg * 4 + 2][i] * w;
        a3  += sx[rg * 4 + 3][i] * w;
    }
    g_h[(row0 + rg * 4 + 0) * D + o] = a0;
    g_h[(row0 + rg * 4 + 1) * D + o] = a1c;
    g_h[(row0 + rg * 4 + 2) * D + o] = a2c;
    g_h[(row0 + rg * 4 + 3) * D + o] = a3;
    sh[rg * 4 + 0][o] = a0;
    sh[rg * 4 + 1][o] = a1c;
    sh[rg * 4 + 2][o] = a2c;
    sh[rg * 4 + 3][o] = a3;
    __syncthreads();
    // f1/f2 per row: 8 warps x 2 rows
    int w = tid >> 5, lane = tid & 31;
#pragma unroll
    for (int q = 0; q < 2; q++) {
        int r = w * 2 + q;
        float h0 = sh[r][lane], h1 = sh[r][lane + 32];
        float s1 = h0 * a1[lane] + h1 * a1[lane + 32];
        float s2 = h0 * a2[lane] + h1 * a2[lane + 32];
#pragma unroll
        for (int off = 16; off; off >>= 1) {
            s1 += __shfl_down_sync(0xFFFFFFFFu, s1, off);
            s2 += __shfl_down_sync(0xFFFFFFFFu, s2, off);
        }
        if (lane == 0) {
            int row = row0 + r;
            float f1v = s1 + b1[0], f2v = s2 + b2[0];
            g_f1[row] = f1v;
            g_f2[row] = f2v;
            unsigned u = __float_as_uint(f2v);
            u = (u >> 31) ? ~u : (u | 0x80000000u);   // order-preserving map
            g_key[row] = ((unsigned long long)u << 13) | (unsigned)row;  // tie-break
            g_rank[row] = 0;
        }
    }
}

// ---------------- k2: rank sort (counting) ----------------
// 512 blocks: (element-block eb of 128) x (comparison-chunk cb of 1024)
__global__ void kRank() {
    __shared__ unsigned long long sk[1024];
    int tid = threadIdx.x;  // 128
    int eb = blockIdx.x >> 3, cb = blockIdx.x & 7;
    int i = eb * 128 + tid;
    unsigned long long ki = g_key[i];
#pragma unroll
    for (int m = 0; m < 8; m++) sk[tid + m * 128] = g_key[cb * 1024 + tid + m * 128];
    __syncthreads();
    int cnt = 0;
#pragma unroll 8
    for (int j = 0; j < 1024; j++) cnt += (sk[j] < ki);
    atomicAdd(&g_rank[i], cnt);
}

// ---------------- k3: scatter into sorted order + exp weights ----------------
__global__ void kScatter() {
    int i = blockIdx.x * 256 + threadIdx.x;
    int r = g_rank[i];
    float f = g_f2[i];
    g_perm[r] = i;
    g_f2s[r] = f;
    g_wlo[r] = expf(ALPHA * f);
    g_whi[r] = expf(f);
}

// ---------------- k4: S1 — per-chunk local scans (smem tile) ----------------
__global__ void kS1() {
    extern __shared__ float tile[];        // tLo[CS*D] then tHi[CS*D] = 64KB
    float* tLo = tile;
    float* tHi = tile + CS * D;
    __shared__ int   sperm[CS];
    __shared__ float slo[CS], shi[CS];
    int tid = threadIdx.x;   // 256
    int c = blockIdx.x;
    int j0 = c * CS;
    if (tid < CS) {
        sperm[tid] = g_perm[j0 + tid];
        slo[tid] = g_wlo[j0 + tid];
        shi[tid] = g_whi[j0 + tid];
    }
    __syncthreads();
    for (int idx = tid; idx < CS * D; idx += 256) {
        int j = idx >> 6;
        float hv = g_h[sperm[j] * D + (idx & 63)];
        tLo[idx] = slo[j] * hv;
        tHi[idx] = shi[j] * hv;
    }
    __syncthreads();
    if (tid < 64) {                       // forward column scan
        int d = tid;
        if (c == 0) g_LoP[d] = 0.f;
        float run = 0.f;
#pragma unroll 8
        for (int j = 0; j < CS; j++) {
            run += tLo[j * D + d];
            g_LoP[(j0 + j + 1) * D + d] = run;
        }
        g_ofLo[d * NC + c] = run;         // chunk total
    } else if (tid < 128) {               // backward column scan
        int d = tid - 64;
        if (c == NC - 1) g_HiS[NN * D + d] = 0.f;
        float run = 0.f;
#pragma unroll 8
        for (int j = CS - 1; j >= 0; j--) {
            run += tHi[j * D + d];
            g_HiS[(j0 + j) * D + d] = run;
        }
        g_ofHi[d * NC + c] = run;
    } else if (tid == 128) {              // zLo forward
        if (c == 0) g_zLo[0] = 0.f;
        float run = 0.f;
        for (int j = 0; j < CS; j++) { run += slo[j]; g_zLo[j0 + j + 1] = run; }
        g_ofzLo[c] = run;
    } else if (tid == 129) {              // zHi backward
        if (c == NC - 1) g_zHi[NN] = 0.f;
        float run = 0.f;
        for (int j = CS - 1; j >= 0; j--) { run += shi[j]; g_zHi[j0 + j] = run; }
        g_ofzHi[c] = run;
    }
}

// ---------------- k5: S2 — scan chunk totals -> exclusive offsets (in place) ----------------
__global__ void kS2() {
    int t = blockIdx.x * 4 + (threadIdx.x >> 5);
    int lane = threadIdx.x & 31;
    if (t >= 130) return;
    const unsigned F = 0xFFFFFFFFu;
    float* base;
    bool fwd;
    if (t < 64)       { base = g_ofLo + t * NC;        fwd = true;  }
    else if (t < 128) { base = g_ofHi + (t - 64) * NC; fwd = false; }
    else if (t == 128){ base = g_ofzLo;                fwd = true;  }
    else              { base = g_ofzHi;                fwd = false; }
    float v0 = base[lane], v1 = base[lane + 32];
    if (fwd) {
        float x0 = v0;
#pragma unroll
        for (int o = 1; o < 32; o <<= 1) { float s = __shfl_up_sync(F, x0, o); if (lane >= o) x0 += s; }
        float tot0 = __shfl_sync(F, x0, 31);
        float x1 = v1;
#pragma unroll
        for (int o = 1; o < 32; o <<= 1) { float s = __shfl_up_sync(F, x1, o); if (lane >= o) x1 += s; }
        base[lane] = x0 - v0;                 // exclusive prefix
        base[lane + 32] = tot0 + x1 - v1;
    } else {
        float x1 = v1;
#pragma unroll
        for (int o = 1; o < 32; o <<= 1) { float s = __shfl_down_sync(F, x1, o); if (lane + o < 32) x1 += s; }
        float tot1 = __shfl_sync(F, x1, 0);
        float x0 = v0;
#pragma unroll
        for (int o = 1; o < 32; o <<= 1) { float s = __shfl_down_sync(F, x0, o); if (lane + o < 32) x0 += s; }
        base[lane] = x0 - v0 + tot1;          // exclusive suffix
        base[lane + 32] = x1 - v1;
    }
}

// ---------------- k6: per-row combine + ELU ----------------
__global__ void kOut(float* __restrict__ out) {
    int w = threadIdx.x >> 5, lane = threadIdx.x & 31;
    int i = blockIdx.x * 8 + w;
    float f1 = g_f1[i];
    float thr = -f1;
    int k = 0;
    if (lane == 0) {
        int lo = 0, hi = NN;
        while (lo < hi) { int m = (lo + hi) >> 1; if (g_f2s[m] <= thr) lo = m + 1; else hi = m; }
        k = lo;
    }
    k = __shfl_sync(0xFFFFFFFFu, k, 0);
    int ckLo = (k == 0) ? 0 : ((k - 1) >> 7);
    int ckHi = k >> 7;
    bool hasHi = (k < NN);
    float e1 = expf(f1), ea = expf(ALPHA * f1);
    float zLoV = g_zLo[k] + g_ofzLo[ckLo];
    float zHiV = hasHi ? (g_zHi[k] + g_ofzHi[ckHi]) : 0.f;
    float inv = 1.0f / (e1 * zHiV + ea * zLoV);
#pragma unroll
    for (int p = 0; p < 2; p++) {
        int d = lane + 32 * p;
        float lo = g_LoP[k * D + d] + g_ofLo[d * NC + ckLo];
        float hi = hasHi ? (g_HiS[k * D + d] + g_ofHi[d * NC + ckHi]) : 0.f;
        float r = (e1 * hi + ea * lo) * inv;
        out[i * D + d] = (r > 0.f) ? r : (expf(r) - 1.f);
    }
}

extern "C" void kernel_launch(void* const* d_in, const int* in_sizes, int n_in,
                              void* d_out, int out_size) {
    const float* x  = (const float*)d_in[0];
    const float* Wt = (const float*)d_in[1];
    const float* a1 = (const float*)d_in[2];
    const float* b1 = (const float*)d_in[3];
    const float* a2 = (const float*)d_in[4];
    const float* b2 = (const float*)d_in[5];
    float* out = (float*)d_out;

    cudaFuncSetAttribute(kS1, cudaFuncAttributeMaxDynamicSharedMemorySize, CS * D * 2 * 4);

    k1<<<NN / 16, 256>>>(x, Wt, a1, b1, a2, b2);
    kRank<<<512, 128>>>();
    kScatter<<<32, 256>>>();
    kS1<<<NC, 256, CS * D * 2 * 4>>>();
    kS2<<<33, 128>>>();
    kOut<<<NN / 8, 256>>>(out);
}